// round 1
// baseline (speedup 1.0000x reference)
#include <cuda_runtime.h>
#include <math.h>

#define NB 16
#define NH 320
#define NW 320
#define NPIX (NB * NH * NW)
#define BIGF 1e12f
#define INV_N (1.0f / (float)NPIX)

// Scratch: squared row-distances (pass-1 output) for 4 fields:
// 0: pred fg-EDT seed dist (nearest mask==0 along row)
// 1: pred bg-EDT seed dist (nearest mask==1 along row)
// 2: tgt  fg-EDT
// 3: tgt  bg-EDT
__device__ float g_row2[4][NPIX];
__device__ int g_hasfg[2][NB];

__global__ void hd_zero_kernel(float* out) {
    int i = threadIdx.x;
    if (i == 0) out[0] = 0.0f;
    if (i < NB) { g_hasfg[0][i] = 0; g_hasfg[1][i] = 0; }
}

// One block = one row of one image. 320 threads.
__global__ void hd_pass1_kernel(const float* __restrict__ pred,
                                const float* __restrict__ tgt) {
    const int y = blockIdx.x;
    const int n = blockIdx.y;
    const int x = threadIdx.x;

    __shared__ unsigned char mp[NW];
    __shared__ unsigned char mt[NW];

    const int base = (n * NH + y) * NW;
    const float pv = pred[base + x];
    const float tv = tgt[base + x];
    const unsigned char bp = (pv > 0.5f) ? 1 : 0;
    const unsigned char bt = (tv > 0.5f) ? 1 : 0;
    mp[x] = bp;
    mt[x] = bt;

    const int anyp = __syncthreads_or((int)bp);
    const int anyt = __syncthreads_or((int)bt);
    if (x == 0) {
        if (anyp) atomicOr(&g_hasfg[0][n], 1);
        if (anyt) atomicOr(&g_hasfg[1][n], 1);
    }

    // Expanding search for nearest 0 (dF) and nearest 1 (dT) in this row.
    // pred:
    {
        int dF = -1, dT = -1;
        for (int d = 0; d < NW; d++) {
            int a = (x - d >= 0) ? (int)mp[x - d] : -1;
            int b = (x + d < NW) ? (int)mp[x + d] : -1;
            if (dF < 0 && (a == 0 || b == 0)) dF = d;
            if (dT < 0 && (a == 1 || b == 1)) dT = d;
            if (dF >= 0 && dT >= 0) break;
        }
        g_row2[0][base + x] = (dF < 0) ? BIGF : (float)(dF * dF);
        g_row2[1][base + x] = (dT < 0) ? BIGF : (float)(dT * dT);
    }
    // target:
    {
        int dF = -1, dT = -1;
        for (int d = 0; d < NW; d++) {
            int a = (x - d >= 0) ? (int)mt[x - d] : -1;
            int b = (x + d < NW) ? (int)mt[x + d] : -1;
            if (dF < 0 && (a == 0 || b == 0)) dF = d;
            if (dT < 0 && (a == 1 || b == 1)) dT = d;
            if (dF >= 0 && dT >= 0) break;
        }
        g_row2[2][base + x] = (dF < 0) ? BIGF : (float)(dF * dF);
        g_row2[3][base + x] = (dT < 0) ? BIGF : (float)(dT * dT);
    }
}

// Pass 2 along H + fused loss. One block = one row of one image (320 threads),
// each thread walks its column in the 4 scratch fields with early exit.
__global__ void hd_pass2_kernel(const float* __restrict__ pred,
                                const float* __restrict__ tgt,
                                float* __restrict__ out) {
    const int y = blockIdx.x;
    const int n = blockIdx.y;
    const int x = threadIdx.x;

    const int plane = n * NH * NW;
    const int idx = plane + y * NW + x;

    float g[4];
#pragma unroll
    for (int f = 0; f < 4; f++) {
        const float* s = &g_row2[f][plane + x];  // column x, stride NW
        float best = s[y * NW];
        for (int r = 1; r < NH; r++) {
            const float r2 = (float)(r * r);
            if (r2 >= best) break;
            const int ym = y - r;
            const int yp = y + r;
            if (ym >= 0) best = fminf(best, s[ym * NW] + r2);
            if (yp < NH) best = fminf(best, s[yp * NW] + r2);
        }
        g[f] = fminf(best, BIGF);
    }

    // field = sqrt(g_fg) + sqrt(g_bg); dt^2 = field^2 (one term is always 0)
    const float fp = sqrtf(g[0]) + sqrtf(g[1]);
    const float ft = sqrtf(g[2]) + sqrtf(g[3]);
    const float dt2p = g_hasfg[0][n] ? fp * fp : 0.0f;
    const float dt2t = g_hasfg[1][n] ? ft * ft : 0.0f;

    const float e = pred[idx] - tgt[idx];
    float v = e * e * (dt2p + dt2t) * INV_N;

    // Block reduction: warp shuffle + smem across 10 warps, then atomicAdd.
#pragma unroll
    for (int off = 16; off > 0; off >>= 1)
        v += __shfl_down_sync(0xffffffffu, v, off);

    __shared__ float wsum[NW / 32];
    const int lane = x & 31;
    const int wid = x >> 5;
    if (lane == 0) wsum[wid] = v;
    __syncthreads();
    if (x == 0) {
        float s = 0.0f;
#pragma unroll
        for (int i = 0; i < NW / 32; i++) s += wsum[i];
        atomicAdd(out, s);
    }
}

extern "C" void kernel_launch(void* const* d_in, const int* in_sizes, int n_in,
                              void* d_out, int out_size) {
    const float* pred = (const float*)d_in[0];
    const float* tgt  = (const float*)d_in[1];
    float* out = (float*)d_out;

    hd_zero_kernel<<<1, 32>>>(out);

    dim3 grid(NH, NB);
    hd_pass1_kernel<<<grid, NW>>>(pred, tgt);
    hd_pass2_kernel<<<grid, NW>>>(pred, tgt, out);
}

// round 3
// speedup vs baseline: 1.5289x; 1.5289x over previous
#include <cuda_runtime.h>
#include <math.h>

#define NB 16
#define NH 320
#define NW 320
#define NPIX (NB * NH * NW)
#define NWORDS 10            // 320 / 32
#define SENTINEL 20000       // "no seed in this row" distance stand-in
#define INV_N (1.0f / (float)NPIX)

// Packed pass-1 output: one int16 per pixel per image.
//  code > 0 : pixel is fg (mask=1); code = dist to nearest 0 in row (dT = 0)
//  code < 0 : pixel is bg (mask=0); -code = dist to nearest 1 in row (dF = 0)
__device__ short g_code[2][NPIX];
__device__ int g_hasfg[2][NB];   // zero-initialized at module load; OR is idempotent

// Nearest set bit to center (bit 32) of a 64-bit window. Returns -1 if none.
__device__ __forceinline__ int ndist(unsigned long long v) {
    if (!v) return -1;
    unsigned long long t = v >> 32;          // bit 32 -> d=0, bit 33 -> d=1, ...
    int dR = t ? (__ffsll((long long)t) - 1) : 1000;
    unsigned long long u = v << 32;          // bit 31 -> top bit -> d=1, ...
    int dL = u ? (__clzll((long long)u) + 1) : 1000;
    return min(dR, dL);
}

// Rare fallback: nearest bit equal to want_one at distance > 32.
__device__ int far_search(const unsigned int* w, int x, int want_one) {
    for (int d = 33; d < NW; d++) {
        int l = x - d, r = x + d;
        if (l >= 0) { int b = (w[l >> 5] >> (l & 31)) & 1; if (b == want_one) return d; }
        if (r < NW) { int b = (w[r >> 5] >> (r & 31)) & 1; if (b == want_one) return d; }
    }
    return SENTINEL;
}

// One block = one row of one image. 320 threads (10 full warps).
__global__ void hd_pass1_kernel(const float* __restrict__ pred,
                                const float* __restrict__ tgt,
                                float* __restrict__ out) {
    const int y = blockIdx.x;
    const int n = blockIdx.y;
    const int x = threadIdx.x;

    if (y == 0 && n == 0 && x == 0) out[0] = 0.0f;  // pass2 atomics need this

    __shared__ unsigned int wp[NWORDS];
    __shared__ unsigned int wt[NWORDS];

    const int base = (n * NH + y) * NW;
    const int bp = (pred[base + x] > 0.5f) ? 1 : 0;
    const int bt = (tgt[base + x] > 0.5f) ? 1 : 0;

    const unsigned int balp = __ballot_sync(0xffffffffu, bp);
    const unsigned int balt = __ballot_sync(0xffffffffu, bt);
    const int lane = x & 31, wid = x >> 5;
    if (lane == 0) { wp[wid] = balp; wt[wid] = balt; }

    const int anyp = __syncthreads_or(bp);   // also publishes wp/wt
    const int anyt = __syncthreads_or(bt);
    if (x == 0) {
        if (anyp) atomicOr(&g_hasfg[0][n], 1);
        if (anyt) atomicOr(&g_hasfg[1][n], 1);
    }

    // 64-bit window of row bits centered at x (bit 32 = position x).
    const int c = wid, o = lane;
    unsigned long long validw = ~0ULL;
    if (x < 32)  validw <<= (32 - x);
    if (x > 288) validw &= (~0ULL >> (x - 288));

    {   // pred
        unsigned int w0 = (c > 0) ? wp[c - 1] : 0u;
        unsigned int w1 = wp[c];
        unsigned int w2 = (c < NWORDS - 1) ? wp[c + 1] : 0u;
        unsigned long long lo = (unsigned long long)w0 | ((unsigned long long)w1 << 32);
        unsigned long long win = lo >> o;
        if (o) win |= (unsigned long long)w2 << (64 - o);
        int code;
        if (bp) {  // need nearest 0
            int d = ndist((~win) & validw);
            if (d < 0) d = far_search(wp, x, 0);
            code = d;
        } else {   // need nearest 1
            int d = ndist(win & validw);
            if (d < 0) d = far_search(wp, x, 1);
            code = -d;
        }
        g_code[0][base + x] = (short)code;
    }
    {   // target
        unsigned int w0 = (c > 0) ? wt[c - 1] : 0u;
        unsigned int w1 = wt[c];
        unsigned int w2 = (c < NWORDS - 1) ? wt[c + 1] : 0u;
        unsigned long long lo = (unsigned long long)w0 | ((unsigned long long)w1 << 32);
        unsigned long long win = lo >> o;
        if (o) win |= (unsigned long long)w2 << (64 - o);
        int code;
        if (bt) {
            int d = ndist((~win) & validw);
            if (d < 0) d = far_search(wt, x, 0);
            code = d;
        } else {
            int d = ndist(win & validw);
            if (d < 0) d = far_search(wt, x, 1);
            code = -d;
        }
        g_code[1][base + x] = (short)code;
    }
}

// Column walk for the single active field at this pixel.
// col points at element (row 0, column x); c is the center code.
__device__ __forceinline__ float walk_col(const short* __restrict__ col, int y, int c) {
    const bool pos = (c > 0);        // active field: fg if pos, bg if neg
    const int a = pos ? c : -c;      // a >= 1 always
    float best = (float)a * (float)a;
    for (int r = 1; r < NH; r++) {
        const float r2 = (float)(r * r);
        if (r2 >= best) break;       // ~75% of pixels exit at r=1
        const int ym = y - r, yp = y + r;
        if (ym >= 0) {
            int v = col[ym * NW];
            int d = pos ? max(v, 0) : max(-v, 0);
            best = fminf(best, (float)d * (float)d + r2);
        }
        if (yp < NH) {
            int v = col[yp * NW];
            int d = pos ? max(v, 0) : max(-v, 0);
            best = fminf(best, (float)d * (float)d + r2);
        }
    }
    return best;  // squared EDT of active field; complementary field is 0 here
}

// Pass 2 + fused loss. One block = one row of one image, 320 threads.
__global__ void hd_pass2_kernel(const float* __restrict__ pred,
                                const float* __restrict__ tgt,
                                float* __restrict__ out) {
    const int y = blockIdx.x;
    const int n = blockIdx.y;
    const int x = threadIdx.x;

    const int plane = n * NH * NW;
    const int idx = plane + y * NW + x;

    // Issue all independent loads first.
    const float pv = pred[idx];
    const float tv = tgt[idx];
    const int cp = g_code[0][idx];
    const int ct = g_code[1][idx];

    const float gp = walk_col(&g_code[0][plane + x], y, cp);
    const float gt = walk_col(&g_code[1][plane + x], y, ct);

    // field = sqrt(g_active) + sqrt(0); dt^2 = g_active (one term always 0)
    const float dt2p = g_hasfg[0][n] ? gp : 0.0f;
    const float dt2t = g_hasfg[1][n] ? gt : 0.0f;

    const float e = pv - tv;
    float v = e * e * (dt2p + dt2t) * INV_N;

#pragma unroll
    for (int off = 16; off > 0; off >>= 1)
        v += __shfl_down_sync(0xffffffffu, v, off);

    __shared__ float wsum[NW / 32];
    const int lane = x & 31;
    const int wid = x >> 5;
    if (lane == 0) wsum[wid] = v;
    __syncthreads();
    if (x == 0) {
        float s = 0.0f;
#pragma unroll
        for (int i = 0; i < NW / 32; i++) s += wsum[i];
        atomicAdd(out, s);
    }
}

extern "C" void kernel_launch(void* const* d_in, const int* in_sizes, int n_in,
                              void* d_out, int out_size) {
    const float* pred = (const float*)d_in[0];
    const float* tgt  = (const float*)d_in[1];
    float* out = (float*)d_out;

    dim3 grid(NH, NB);
    hd_pass1_kernel<<<grid, NW>>>(pred, tgt, out);
    hd_pass2_kernel<<<grid, NW>>>(pred, tgt, out);
}

// round 7
// speedup vs baseline: 1.5565x; 1.0180x over previous
#include <cuda_runtime.h>
#include <math.h>

#define NB 16
#define NH 320
#define NW 320
#define NPIX (NB * NH * NW)
#define NWORDS 10            // 320 / 32
#define SENTINEL 20000       // "no seed in this row" distance stand-in
#define INV_N (1.0f / (float)NPIX)

// Packed pass-1 output: short2 per pixel = (pred code, target code).
//  code > 0 : pixel is fg (mask=1); code = dist to nearest 0 in row (bg-row-dist = 0)
//  code < 0 : pixel is bg (mask=0); -code = dist to nearest 1 in row (fg-row-dist = 0)
__device__ short2 g_code2[NPIX];
__device__ int g_hasfg[2][NB];   // zero-init at load; OR is idempotent across replays

// Nearest set bit to center (bit 32) of a 64-bit window. Returns -1 if none.
__device__ __forceinline__ int ndist(unsigned long long v) {
    if (!v) return -1;
    unsigned long long t = v >> 32;
    int dR = t ? (__ffsll((long long)t) - 1) : 1000;
    unsigned long long u = v << 32;
    int dL = u ? (__clzll((long long)u) + 1) : 1000;
    return min(dR, dL);
}

// Rare fallback: nearest bit equal to want_one at distance > 32.
__device__ int far_search(const unsigned int* w, int x, int want_one) {
    for (int d = 33; d < NW; d++) {
        int l = x - d, r = x + d;
        if (l >= 0) { int b = (w[l >> 5] >> (l & 31)) & 1; if (b == want_one) return d; }
        if (r < NW) { int b = (w[r >> 5] >> (r & 31)) & 1; if (b == want_one) return d; }
    }
    return SENTINEL;
}

__device__ __forceinline__ int row_code(const unsigned int* w, int c, int o,
                                        unsigned long long validw, int bit, int x) {
    unsigned int w0 = (c > 0) ? w[c - 1] : 0u;
    unsigned int w1 = w[c];
    unsigned int w2 = (c < NWORDS - 1) ? w[c + 1] : 0u;
    unsigned long long lo = (unsigned long long)w0 | ((unsigned long long)w1 << 32);
    unsigned long long win = lo >> o;
    if (o) win |= (unsigned long long)w2 << (64 - o);
    if (bit) {                       // fg pixel: nearest 0
        int d = ndist((~win) & validw);
        if (d < 0) d = far_search(w, x, 0);
        return d;
    } else {                         // bg pixel: nearest 1
        int d = ndist(win & validw);
        if (d < 0) d = far_search(w, x, 1);
        return -d;
    }
}

// One block = one row of one image. 320 threads (10 full warps).
__global__ void __launch_bounds__(NW)
hd_pass1_kernel(const float* __restrict__ pred,
                const float* __restrict__ tgt,
                float* __restrict__ out) {
    const int y = blockIdx.x;
    const int n = blockIdx.y;
    const int x = threadIdx.x;

    if (y == 0 && n == 0 && x == 0) out[0] = 0.0f;  // pass2 atomics need this

    __shared__ unsigned int wp[NWORDS];
    __shared__ unsigned int wt[NWORDS];

    const int base = (n * NH + y) * NW;
    const int bp = (pred[base + x] > 0.5f) ? 1 : 0;
    const int bt = (tgt[base + x] > 0.5f) ? 1 : 0;

    const unsigned int balp = __ballot_sync(0xffffffffu, bp);
    const unsigned int balt = __ballot_sync(0xffffffffu, bt);
    const int lane = x & 31, wid = x >> 5;
    if (lane == 0) { wp[wid] = balp; wt[wid] = balt; }

    __syncthreads();   // publish wp/wt

    // Bitwise-correct has-fg flags from the ballot words (thread 0 only).
    if (x == 0) {
        unsigned int pa = 0u, ta = 0u;
#pragma unroll
        for (int i = 0; i < NWORDS; i++) { pa |= wp[i]; ta |= wt[i]; }
        if (pa) atomicOr(&g_hasfg[0][n], 1);
        if (ta) atomicOr(&g_hasfg[1][n], 1);
    }

    unsigned long long validw = ~0ULL;
    if (x < 32)  validw <<= (32 - x);
    if (x > 288) validw &= (~0ULL >> (x - 288));

    const int cP = row_code(wp, wid, lane, validw, bp, x);
    const int cT = row_code(wt, wid, lane, validw, bt, x);
    g_code2[base + x] = make_short2((short)cP, (short)cT);
}

// Pass 2 + fused loss. One block = one row of one image, 320 threads.
// Single merged integer walk over both fields.
__global__ void __launch_bounds__(NW)
hd_pass2_kernel(const float* __restrict__ pred,
                const float* __restrict__ tgt,
                float* __restrict__ out) {
    const int y = blockIdx.x;
    const int n = blockIdx.y;
    const int x = threadIdx.x;

    const int plane = n * NH * NW;
    const int idx = plane + y * NW + x;

    const float pv = pred[idx];
    const float tv = tgt[idx];
    const short2 c0 = g_code2[idx];

    const int cp = c0.x, ct = c0.y;
    const int sP = (cp > 0) ? 1 : -1;     // active field selector per column
    const int sT = (ct > 0) ? 1 : -1;
    const int aP = abs(cp), aT = abs(ct);
    int bestP = aP * aP;
    int bestT = aT * aT;
    int bmax = max(bestP, bestT);

    const int rUp = y;            // up neighbor valid while r <= y
    const int rDn = NH - 1 - y;   // down neighbor valid while r <= NH-1-y

    const short2* up = g_code2 + plane + x + (y - 1) * NW;
    const short2* dn = g_code2 + plane + x + (y + 1) * NW;

    int r = 1, r2 = 1;
    while (r2 < bmax) {
        if (r <= rUp) {
            const short2 v = *up;
            const int dP = max(sP * (int)v.x, 0);
            const int dT = max(sT * (int)v.y, 0);
            bestP = min(bestP, dP * dP + r2);
            bestT = min(bestT, dT * dT + r2);
        }
        if (r <= rDn) {
            const short2 v = *dn;
            const int dP = max(sP * (int)v.x, 0);
            const int dT = max(sT * (int)v.y, 0);
            bestP = min(bestP, dP * dP + r2);
            bestT = min(bestT, dT * dT + r2);
        }
        up -= NW; dn += NW;
        bmax = max(bestP, bestT);
        r += 1;
        r2 += (r << 1) - 1;               // r2 = r*r incrementally
    }

    // dt^2 = active-field squared EDT (complementary field is 0 at every pixel)
    const float dt2p = g_hasfg[0][n] ? (float)bestP : 0.0f;
    const float dt2t = g_hasfg[1][n] ? (float)bestT : 0.0f;

    const float e = pv - tv;
    float v = e * e * (dt2p + dt2t) * INV_N;

#pragma unroll
    for (int off = 16; off > 0; off >>= 1)
        v += __shfl_down_sync(0xffffffffu, v, off);

    __shared__ float wsum[NW / 32];
    const int lane = x & 31;
    const int wid = x >> 5;
    if (lane == 0) wsum[wid] = v;
    __syncthreads();
    if (x == 0) {
        float s = 0.0f;
#pragma unroll
        for (int i = 0; i < NW / 32; i++) s += wsum[i];
        atomicAdd(out, s);
    }
}

extern "C" void kernel_launch(void* const* d_in, const int* in_sizes, int n_in,
                              void* d_out, int out_size) {
    const float* pred = (const float*)d_in[0];
    const float* tgt  = (const float*)d_in[1];
    float* out = (float*)d_out;

    dim3 grid(NH, NB);
    hd_pass1_kernel<<<grid, NW>>>(pred, tgt, out);
    hd_pass2_kernel<<<grid, NW>>>(pred, tgt, out);
}